// round 17
// baseline (speedup 1.0000x reference)
#include <cuda_runtime.h>
#include <cuda_bf16.h>
#include <stdint.h>

// Problem constants
#define BB   4
#define H    352
#define W    1216
#define HW   (H*W)               // 428032
#define NPX  (BB*HW)             // 1712128
#define PAD  4
#define HP   (H + 2*PAD)         // 360
#define WP   (W + 2*PAD)         // 1224
#define NPAD (BB*HP*WP)          // 1762560
#define PROP 18

// Tile geometry for iter kernel: 32x8 pixels, halo 4 -> 16x40 floats smem.
#define TBX  32
#define TBY  8
#define THAL 4
#define TROWS (TBY + 2*THAL)     // 16
#define TCOLS (TBX + 2*THAL)     // 40

typedef unsigned long long u64;

// Packed tap record (u64), all RELATIVE to the pixel:
//  [0,6)    : dyr + 32   (row displacement of top-left corner, [-32,31])
//  [6,16)   : dxr + 512  (col displacement, [-512,511])
//  [16,29)  : fy  (13-bit fraction, /8192)
//  [29,42)  : fx  (13-bit fraction, /8192)
//  [42,59)  : aff (17-bit fixed point, (q-65536)/32768)

__device__ __align__(1024) float g_buf[2][NPAD];
__device__ __align__(1024) uint4 d_meta[4 * NPX];

// ---------------------------------------------------------------------------
// Packed fp32x2 helpers (FFMA2 only via PTX)
__device__ __forceinline__ u64 pack2(float lo, float hi) {
    u64 r; asm("mov.b64 %0, {%1, %2};" : "=l"(r) : "f"(lo), "f"(hi)); return r;
}
__device__ __forceinline__ void unpack2(u64 v, float& lo, float& hi) {
    asm("mov.b64 {%0, %1}, %2;" : "=f"(lo), "=f"(hi) : "l"(v));
}
__device__ __forceinline__ u64 fma2(u64 a, u64 b, u64 c) {
    u64 d; asm("fma.rn.f32x2 %0, %1, %2, %3;" : "=l"(d) : "l"(a), "l"(b), "l"(c));
    return d;
}

// ---------------------------------------------------------------------------
__global__ void zero_kernel() {
    int i = blockIdx.x * blockDim.x + threadIdx.x;
    if (i < 2 * NPAD) (&g_buf[0][0])[i] = 0.0f;
}

__global__ void init_kernel(const float* __restrict__ feat,
                            const float* __restrict__ conf) {
    int p = blockIdx.x * blockDim.x + threadIdx.x;
    if (p >= NPX) return;
    int b = p / HW;
    int r = p - b * HW;
    int y = r / W;
    int x = r - y * W;
    int pidx = (b * HP + y + PAD) * WP + (x + PAD);
    g_buf[0][pidx] = feat[p] * conf[p];
}

// ---------------------------------------------------------------------------
__device__ __forceinline__ u64 encode_tap(
        int y, int x, int j, float dy, float dx, float aff)
{
    float ys = (float)(y + j / 3 - 1) + dy;
    float xs = (float)(x + j % 3 - 1) + dx;
    float y0f = floorf(ys);
    float x0f = floorf(xs);
    float fy = ys - y0f;
    float fx = xs - x0f;
    int iy = (int)fmaxf(fminf(y0f, 1.0e6f), -1.0e6f);
    int ix = (int)fmaxf(fminf(x0f, 1.0e6f), -1.0e6f);
    // absolute clamp into padded box (out-of-image -> guaranteed-zero halo)
    int yp = min(max(iy + PAD, 0), HP - 2);
    int xp = min(max(ix + PAD, 0), WP - 2);
    // relative displacement fields (clamped to field range, then re-clamped
    // to stay inside the padded box; only >60-sigma offsets are affected)
    int dyr = yp - (y + PAD);
    dyr = min(max(dyr, -32), 31);
    dyr = min(max(dyr, -(y + PAD)), HP - 2 - (y + PAD));
    int dxr = xp - (x + PAD);
    dxr = min(max(dxr, -512), 511);
    dxr = min(max(dxr, -(x + PAD)), WP - 2 - (x + PAD));
    int fu = (int)(fy * 8192.0f + 0.5f); fu = min(max(fu, 0), 8191);
    int fv = (int)(fx * 8192.0f + 0.5f); fv = min(max(fv, 0), 8191);
    int qa = (int)floorf(aff * 32768.0f + 0.5f) + 65536;
    qa = min(max(qa, 0), 131071);
    return (u64)(dyr + 32) | ((u64)(dxr + 512) << 6)
         | ((u64)fu << 16) | ((u64)fv << 29) | ((u64)qa << 42);
}

// TGASS normalization + encode + store for one f32x2 pixel-pair lane.
__device__ __forceinline__ void epilogue_pair(const u64* acc, int p0,
                                              int y, int x, float inv_scale) {
    float a0[8], a1[8];
    float s0 = 0.0f, s1 = 0.0f;
#pragma unroll
    for (int k = 0; k < 8; k++) {
        float lo, hi;
        unpack2(acc[16 + k], lo, hi);
        a0[k] = tanhf(lo) * inv_scale;
        a1[k] = tanhf(hi) * inv_scale;
        s0 += fabsf(a0[k]);
        s1 += fabsf(a1[k]);
    }
    s0 += 1e-4f; if (s0 < 1.0f) s0 = 1.0f;
    s1 += 1e-4f; if (s1 < 1.0f) s1 = 1.0f;
    float i0 = 1.0f / s0, i1 = 1.0f / s1;
#pragma unroll
    for (int k = 0; k < 8; k++) { a0[k] *= i0; a1[k] *= i1; }

#pragma unroll
    for (int q = 0; q < 4; q++) {
        u64 r00, r01, r10, r11;
#pragma unroll
        for (int e = 0; e < 2; e++) {
            int k = 2 * q + e;
            int j = (k < 4) ? k : k + 1;
            float dy0, dy1, dx0, dx1;
            unpack2(acc[2 * k],     dy0, dy1);
            unpack2(acc[2 * k + 1], dx0, dx1);
            u64 rp0 = encode_tap(y, x,     j, dy0, dx0, a0[k]);
            u64 rp1 = encode_tap(y, x + 1, j, dy1, dx1, a1[k]);
            if (e == 0) { r00 = rp0; r10 = rp1; }
            else        { r01 = rp0; r11 = rp1; }
        }
        d_meta[q * NPX + p0] = make_uint4((unsigned)r00, (unsigned)(r00 >> 32),
                                          (unsigned)r01, (unsigned)(r01 >> 32));
        d_meta[q * NPX + p0 + 1] = make_uint4((unsigned)r10, (unsigned)(r10 >> 32),
                                              (unsigned)r11, (unsigned)(r11 >> 32));
    }
}

// Conv(8 -> 24, 3x3, pad 1) via packed f32x2 FFMA2; 4 pixels / thread.
// Weights point-major in smem as pre-duplicated (w,w) u64 pairs (LDS.128).
__global__ __launch_bounds__(128)
void conv_meta_kernel(const float* __restrict__ guid,
                      const float* __restrict__ w_oa,
                      const float* __restrict__ b_oa,
                      const float* __restrict__ aff_scale) {
    __shared__ __align__(16) double2 wsd[864];   // [pt*12 + c/2]
    __shared__ float bs[24];
    for (int idx = threadIdx.x; idx < 864; idx += blockDim.x) {
        int pt = idx / 12;
        int c  = 2 * (idx - pt * 12);
        float w0 = w_oa[c * 72 + pt];
        float w1 = w_oa[(c + 1) * 72 + pt];
        wsd[idx] = make_double2(__longlong_as_double(pack2(w0, w0)),
                                __longlong_as_double(pack2(w1, w1)));
    }
    if (threadIdx.x < 24) bs[threadIdx.x] = b_oa[threadIdx.x];
    __syncthreads();

    int t  = blockIdx.x * blockDim.x + threadIdx.x;
    int p0 = 4 * t;
    if (p0 >= NPX) return;
    int b = p0 / HW;
    int r = p0 - b * HW;
    int y = r / W;
    int x = r - y * W;   // x % 4 == 0: 4 px same row

    u64 accA[24], accB[24];   // accA = (px0,px1), accB = (px2,px3)
#pragma unroll
    for (int c = 0; c < 24; c++) {
        u64 bb2 = pack2(bs[c], bs[c]);
        accA[c] = bb2;
        accB[c] = bb2;
    }

    const float* gb = guid + (size_t)b * 8 * HW;
    for (int i = 0; i < 8; i++) {
        const float* gch = gb + i * HW;
#pragma unroll
        for (int u = 0; u < 3; u++) {
            int yy = y + u - 1;
            bool yv = (yy >= 0) && (yy < H);
            const float* grow = gch + yy * W;
            float v[6];
#pragma unroll
            for (int q = 0; q < 6; q++) {
                int xx = x + q - 1;
                v[q] = (yv && xx >= 0 && xx < W) ? grow[xx] : 0.0f;
            }
#pragma unroll
            for (int kx = 0; kx < 3; kx++) {
                u64 vA = pack2(v[kx],     v[kx + 1]);
                u64 vB = pack2(v[kx + 2], v[kx + 3]);
                const double2* wrow = &wsd[(i * 9 + u * 3 + kx) * 12];
#pragma unroll
                for (int c2 = 0; c2 < 12; c2++) {
                    double2 wd = wrow[c2];              // LDS.128 broadcast
                    u64 wa = __double_as_longlong(wd.x);
                    u64 wb = __double_as_longlong(wd.y);
                    accA[2 * c2]     = fma2(vA, wa, accA[2 * c2]);
                    accB[2 * c2]     = fma2(vB, wa, accB[2 * c2]);
                    accA[2 * c2 + 1] = fma2(vA, wb, accA[2 * c2 + 1]);
                    accB[2 * c2 + 1] = fma2(vB, wb, accB[2 * c2 + 1]);
                }
            }
        }
    }

    float inv_scale = 1.0f / (aff_scale[0] + 1e-8f);
    epilogue_pair(accA, p0,     y, x,     inv_scale);
    epilogue_pair(accB, p0 + 2, y, x + 2, inv_scale);
}

// ---------------------------------------------------------------------------
// One propagation step, tiled. Block = 32x8 px; smem tile 16x40 floats of the
// padded input covering tile+halo4. In-tile taps (>=99.999%) gather from
// smem; rare far taps fall back to global. Center aff = 1 - sum(taps).
__global__ __launch_bounds__(256)
void iter_kernel(const float* __restrict__ conf,
                 float* __restrict__ out, int sel, int last) {
    __shared__ float s[TROWS * TCOLS];

    int tx = threadIdx.x;            // 0..31
    int ty = threadIdx.y;            // 0..7
    int x0 = blockIdx.x * TBX;
    int y0 = blockIdx.y * TBY;
    int b  = blockIdx.z;

    const float* __restrict__ gin = g_buf[sel];
    // Tile origin in padded coords: row y0+PAD-THAL = y0, col x0+PAD-THAL = x0
    const float* tbase = gin + ((size_t)b * HP + y0) * WP + x0;

    int tid = ty * TBX + tx;
    for (int i = tid; i < TROWS * TCOLS; i += TBX * TBY) {
        int rr = i / TCOLS;
        int cc = i - rr * TCOLS;
        s[i] = tbase[rr * WP + cc];
    }
    __syncthreads();

    int y = y0 + ty;
    int x = x0 + tx;
    int p = b * HW + y * W + x;
    int cidx = (b * HP + y + PAD) * WP + (x + PAD);

    float acc = 0.0f, asum = 0.0f;
#pragma unroll
    for (int q = 0; q < 4; q++) {
        uint4 mm = d_meta[q * NPX + p];
#pragma unroll
        for (int e = 0; e < 2; e++) {
            u64 m = (e == 0)
                ? ((u64)mm.x | ((u64)mm.y << 32))
                : ((u64)mm.z | ((u64)mm.w << 32));
            int dyr = (int)(m & 63u) - 32;
            int dxr = (int)((m >> 6) & 1023u) - 512;
            float fy = (float)((unsigned)(m >> 16) & 8191u) * (1.0f / 8192.0f);
            float fx = (float)((unsigned)(m >> 29) & 8191u) * (1.0f / 8192.0f);
            float av = (float)((int)((unsigned)(m >> 42) & 0x1FFFFu) - 65536)
                       * (1.0f / 32768.0f);
            int rr = ty + THAL + dyr;
            int cc = tx + THAL + dxr;
            float f00, f01, f10, f11;
            if ((unsigned)rr < (unsigned)(TROWS - 1) &&
                (unsigned)cc < (unsigned)(TCOLS - 1)) {
                const float* sp = &s[rr * TCOLS + cc];
                f00 = sp[0];
                f01 = sp[1];
                f10 = sp[TCOLS];
                f11 = sp[TCOLS + 1];
            } else {
                const float* gp = gin + cidx + dyr * WP + dxr;
                f00 = gp[0];
                f01 = gp[1];
                f10 = gp[WP];
                f11 = gp[WP + 1];
            }
            float top = fmaf(fx, f01 - f00, f00);
            float bot = fmaf(fx, f11 - f10, f10);
            acc  = fmaf(av, fmaf(fy, bot - top, top), acc);
            asum += av;
        }
    }
    float fc = s[(ty + THAL) * TCOLS + (tx + THAL)];
    float v = fmaf(1.0f - asum, fc, acc);
    if (last) out[p] = v;
    else      g_buf[sel ^ 1][cidx] = conf[p] * v;
}

// ---------------------------------------------------------------------------
extern "C" void kernel_launch(void* const* d_in, const int* in_sizes, int n_in,
                              void* d_out, int out_size) {
    const float* feat = (const float*)d_in[0];
    const float* guid = (const float*)d_in[1];
    const float* conf = (const float*)d_in[2];
    const float* w    = (const float*)d_in[3];
    const float* bia  = (const float*)d_in[4];
    const float* sc   = (const float*)d_in[5];
    float* out = (float*)d_out;

    const int thr = 256;
    zero_kernel<<<(2 * NPAD + thr - 1) / thr, thr>>>();
    init_kernel<<<(NPX + thr - 1) / thr, thr>>>(feat, conf);
    conv_meta_kernel<<<(NPX / 4 + 127) / 128, 128>>>(guid, w, bia, sc);
    dim3 blk(TBX, TBY);
    dim3 grd(W / TBX, H / TBY, BB);
    for (int t = 0; t < PROP; t++) {
        iter_kernel<<<grd, blk>>>(conf, out, t & 1, t == PROP - 1);
    }
}